// round 15
// baseline (speedup 1.0000x reference)
#include <cuda_runtime.h>
#include <cuda_bf16.h>
#include <math.h>
#include <cstdint>

// Shapes fixed by the problem
#define NN     1024
#define LL     30
#define GG     10000
#define NBATCH 64
#define NT     256     // threads per block
#define GT     256     // genes per block (4 per lane-quad)
#define CH     32      // cells per chunk staged in shared

typedef unsigned long long u64;

// ---- packed f32x2 helpers (sm_103a) ---------------------------------------
#define FMA2(d, a, b, c) \
    asm("fma.rn.f32x2 %0, %1, %2, %3;" : "=l"(d) : "l"(a), "l"(b), "l"(c))
#define ADD2(d, a, b) \
    asm("add.rn.f32x2 %0, %1, %2;" : "=l"(d) : "l"(a), "l"(b))
#define PACK2(d, lo, hi) \
    asm("mov.b64 %0, {%1, %2};" : "=l"(d) : "f"(lo), "f"(hi))
#define UNPACK2(lo, hi, s) \
    asm("mov.b64 {%0, %1}, %2;" : "=f"(lo), "=f"(hi) : "l"(s))

__device__ __forceinline__ float softplus_fast(float x) {
    return fmaxf(x, 0.f) + __logf(1.f + __expf(-fabsf(x)));
}

// ---------------------------------------------------------------------------
// Split-K lane-QUAD decoder. Grid = (40, 64), 256 threads.
// Quad q (lanes 4q..4q+3) owns 4 consecutive genes gbase..gbase+3; lane m of
// the quad holds K-quarter [8m, 8m+8) (k=30,31 are zero pads). Per cell each
// lane: 2 LDS.128 (its 32B of z) + 16 FMA2 (4 genes x 4 pairs, 4 chains),
// then a 2-round butterfly (3 shfl.32) leaves the FULL sum of gene gbase+m
// on lane m. Since gbase+m == g0+tid, bias/softplus/STG are one fully
// coalesced output per lane per cell.
// C-registers drop to 16/thread -> ~50 regs -> 5 blocks/SM (62% occ cap).
// ---------------------------------------------------------------------------
__global__ __launch_bounds__(NT, 5)
void decoder_kernel(const float* __restrict__ z,
                    const int*   __restrict__ bc,
                    const float* __restrict__ sf,
                    const float* __restrict__ W,
                    const float* __restrict__ A,
                    const float* __restrict__ bemb,
                    const float* __restrict__ px_r,
                    float* __restrict__ out) {
    __shared__ __align__(16) float zsh[CH * 32];   // 4096 B
    __shared__ float sfsh[CH];
    __shared__ int   lsh[NN];
    __shared__ int   cnt;

    const int tid = threadIdx.x;
    const int m   = tid & 3;          // K-quarter selector
    const int m1  = m & 1;
    const int m2  = m >> 1;
    const int b   = blockIdx.y;
    const int g0  = blockIdx.x * GT;

    const int gbase = g0 + (tid & ~3);   // quad's first gene
    const int myg   = g0 + tid;          // gene this lane emits (= gbase + m)

    if (tid == 0) cnt = 0;
    if (b == 0) {                        // exp(px_r) tail on b==0 plane
        int i = blockIdx.x * NT + tid;
        if (i < GG) out[(size_t)NN * GG + i] = __expf(px_r[i]);
    }
    __syncthreads();

    // Build this batch's cell list (order irrelevant; each cell owns its row)
    for (int i = tid; i < NN; i += NT)
        if (bc[i] == b) { int p = atomicAdd(&cnt, 1); lsh[p] = i; }

    // Fold this lane's K-quarter of C = A[b,g,:] + W[:,g] for the quad's
    // 4 genes. Pair index pr = m*4+p; pr==15 (k=30,31) is the zero pad.
    u64 C[4][4];
#pragma unroll
    for (int i = 0; i < 4; i++) {
        const int g = gbase + i;
        if (g < GG) {
            const u64* Ar = (const u64*)(A + ((size_t)b * GG + g) * LL);
#pragma unroll
            for (int p = 0; p < 4; p++) {
                const int pr = m * 4 + p;
                if (pr < 15) {
                    u64 w2;
                    PACK2(w2, W[(2 * pr) * GG + g], W[(2 * pr + 1) * GG + g]);
                    ADD2(C[i][p], Ar[pr], w2);
                } else {
                    C[i][p] = 0ULL;
                }
            }
        } else {
#pragma unroll
            for (int p = 0; p < 4; p++) C[i][p] = 0ULL;
        }
    }
    const float bb   = (myg < GG) ? bemb[(size_t)b * GG + myg] : 0.f;
    const bool  emit = (myg < GG);

    __syncthreads();
    const int e = cnt;

    for (int c0 = 0; c0 < e; c0 += CH) {
        const int nch = min(CH, e - c0);
        __syncthreads();   // zsh reuse safety
        // stage z rows (stride 32 floats, pads zeroed); only nch rows
        for (int i = tid; i < nch * 32; i += NT) {
            int j = i >> 5, l = i & 31;
            zsh[i] = (l < LL) ? z[lsh[c0 + j] * LL + l] : 0.f;
        }
        if (tid < nch) sfsh[tid] = sf[lsh[c0 + tid]];
        __syncthreads();

        for (int j = 0; j < nch; j++) {
            // this lane's 32B K-quarter of cell j
            const ulonglong2* zp = (const ulonglong2*)(zsh + j * 32 + m * 8);
            ulonglong2 v0 = zp[0], v1 = zp[1];

            u64 a0 = 0ULL, a1 = 0ULL, a2 = 0ULL, a3 = 0ULL;
            FMA2(a0, C[0][0], v0.x, a0);
            FMA2(a1, C[1][0], v0.x, a1);
            FMA2(a2, C[2][0], v0.x, a2);
            FMA2(a3, C[3][0], v0.x, a3);
            FMA2(a0, C[0][1], v0.y, a0);
            FMA2(a1, C[1][1], v0.y, a1);
            FMA2(a2, C[2][1], v0.y, a2);
            FMA2(a3, C[3][1], v0.y, a3);
            FMA2(a0, C[0][2], v1.x, a0);
            FMA2(a1, C[1][2], v1.x, a1);
            FMA2(a2, C[2][2], v1.x, a2);
            FMA2(a3, C[3][2], v1.x, a3);
            FMA2(a0, C[0][3], v1.y, a0);
            FMA2(a1, C[1][3], v1.y, a1);
            FMA2(a2, C[2][3], v1.y, a2);
            FMA2(a3, C[3][3], v1.y, a3);

            float s0, s1, s2, s3, x, y;
            UNPACK2(x, y, a0); s0 = x + y;
            UNPACK2(x, y, a1); s1 = x + y;
            UNPACK2(x, y, a2); s2 = x + y;
            UNPACK2(x, y, a3); s3 = x + y;

            // Quad reduction, round 1 (xor 1): send the 2 partials the
            // partner keeps (genes 1-m1 and 3-m1); receive its s[m1], s[m1+2].
            float send_lo = m1 ? s0 : s1;          // s[1-m1]
            float send_hi = m1 ? s2 : s3;          // s[3-m1]
            float rlo = __shfl_xor_sync(0xffffffffu, send_lo, 1);
            float rhi = __shfl_xor_sync(0xffffffffu, send_hi, 1);
            float t0 = (m1 ? s1 : s0) + rlo;       // gene m1,   K-half done
            float t1 = (m1 ? s3 : s2) + rhi;       // gene m1+2, K-half done

            // Round 2 (xor 2): keep gene with bit1 == m2, send the other.
            float send2 = m2 ? t0 : t1;
            float r2 = __shfl_xor_sync(0xffffffffu, send2, 2);
            float full = (m2 ? t1 : t0) + r2;      // gene gbase + m == myg

            if (emit) {
                float acc = full + bb;
                out[(size_t)lsh[c0 + j] * GG + myg] = softplus_fast(acc) * sfsh[j];
            }
        }
    }
}

// ---------------------------------------------------------------------------
// Launch. Inputs per metadata order:
//   0: z [N,L] f32        1: batch_covariate [N] i32   2: size_factor [N,1] f32
//   3: W_amat [L,G] f32   4: A_emb [NB,G,L] f32        5: b_emb [NB,G] f32
//   6: px_r [G] f32
// Output: mean [N,G] f32 followed by inverse_dispersion [G] f32.
// ---------------------------------------------------------------------------
extern "C" void kernel_launch(void* const* d_in, const int* in_sizes, int n_in,
                              void* d_out, int out_size) {
    const float* z    = (const float*)d_in[0];
    const int*   bc   = (const int*)  d_in[1];
    const float* sf   = (const float*)d_in[2];
    const float* W    = (const float*)d_in[3];
    const float* A    = (const float*)d_in[4];
    const float* bemb = (const float*)d_in[5];
    const float* pxr  = (const float*)d_in[6];
    float* out = (float*)d_out;

    dim3 grid((GG + GT - 1) / GT, NBATCH);
    decoder_kernel<<<grid, NT>>>(z, bc, sf, W, A, bemb, pxr, out);
}